// round 13
// baseline (speedup 1.0000x reference)
#include <cuda_runtime.h>
#include <cuda_fp16.h>
#include <cstdint>

// ---------------- Problem constants ----------------
#define NROWS   16384
#define QKVW    1536
#define POOLROWS 4064     // coarse rows per bh (levels 1..7)

// ---------------- Device scratch ----------------
__device__ __align__(16) __half g_Yc[(size_t)32 * POOLROWS * 64];   // coarse Y (levels 1..7)
__device__ __align__(16) float  g_Ac[(size_t)32 * POOLROWS];        // coarse Asum

__device__ __align__(16) __half g_qkv16[(size_t)NROWS * QKVW];
__device__ __align__(16) __half g_poolq[(size_t)32 * POOLROWS * 64];
__device__ __align__(16) __half g_poolk[(size_t)32 * POOLROWS * 64];
__device__ __align__(16) __half g_poolv[(size_t)32 * POOLROWS * 64];

__device__ __align__(16) __half g_xh[(size_t)NROWS * 1024];
__device__ __align__(16) __half g_wqh[(size_t)QKVW * 1024];
__device__ __align__(16) __half g_woh[(size_t)1024 * 512];
__device__ __align__(16) __half g_atth[(size_t)NROWS * 512];

// ---------------- helpers ----------------
__device__ __forceinline__ uint32_t smem_to_u32(const void* p) {
    uint32_t a;
    asm("{ .reg .u64 t; cvta.to.shared.u64 t, %1; cvt.u32.u64 %0, t; }" : "=r"(a) : "l"(p));
    return a;
}
__device__ __forceinline__ uint32_t sw128(uint32_t off) {
    return off ^ ((off >> 3) & 0x70);
}

#define LDSM_X4(r0, r1, r2, r3, addr) \
    asm volatile("ldmatrix.sync.aligned.m8n8.x4.shared.b16 {%0,%1,%2,%3}, [%4];" \
        : "=r"(r0), "=r"(r1), "=r"(r2), "=r"(r3) : "r"(addr))
#define LDSM_X4_T(r0, r1, r2, r3, addr) \
    asm volatile("ldmatrix.sync.aligned.m8n8.x4.trans.shared.b16 {%0,%1,%2,%3}, [%4];" \
        : "=r"(r0), "=r"(r1), "=r"(r2), "=r"(r3) : "r"(addr))

__device__ __forceinline__ void mma16816h(float* c, const uint32_t* a, const uint32_t* b) {
    asm volatile(
        "mma.sync.aligned.m16n8k16.row.col.f32.f16.f16.f32 "
        "{%0,%1,%2,%3}, {%4,%5,%6,%7}, {%8,%9}, {%0,%1,%2,%3};"
        : "+f"(c[0]), "+f"(c[1]), "+f"(c[2]), "+f"(c[3])
        : "r"(a[0]), "r"(a[1]), "r"(a[2]), "r"(a[3]), "r"(b[0]), "r"(b[1]));
}

__device__ __forceinline__ uint2 cvt4h(float4 v) {
    uint2 r;
    __half2 lo = __floats2half2_rn(v.x, v.y);
    __half2 hi = __floats2half2_rn(v.z, v.w);
    r.x = *(uint32_t*)&lo;
    r.y = *(uint32_t*)&hi;
    return r;
}

// ---------------- one-shot fp32 -> fp16 conversion ----------------
__global__ __launch_bounds__(256)
void convert_all(const float* __restrict__ x, const float* __restrict__ wq,
                 const float* __restrict__ wo)
{
    int q = blockIdx.x * 256 + threadIdx.x;
    const float* src;
    uint2* dst;
    int local;
    if (q < 4194304) {
        src = x; dst = (uint2*)g_xh; local = q;
    } else if (q < 4194304 + 393216) {
        src = wq; dst = (uint2*)g_wqh; local = q - 4194304;
    } else {
        src = wo; dst = (uint2*)g_woh; local = q - 4194304 - 393216;
    }
    float4 v = *(const float4*)(src + (size_t)local * 4);
    dst[local] = cvt4h(v);
}

// ---------------- fp16 GEMM: 64x128 tile, BK=64, 3 CTAs/SM -----------------
// 8 warps (2m x 4n), warp tile 32x32. 3-stage cp.async.
// Stage (24KB): A @0 (8KB, 64 rows x 128B), B @8192 (16KB, 128 rows x 128B).
#define GS_STAGE 24576
#define GS_SMEM  (3 * GS_STAGE)

template <int OUT16>
__global__ __launch_bounds__(256, 3)
void gemm_fp16(const __half* __restrict__ A, const __half* __restrict__ B,
               const float* __restrict__ bias, float* __restrict__ C,
               __half* __restrict__ C16, int M, int N, int K)
{
    extern __shared__ __align__(1024) char smem[];
    const uint32_t smu = smem_to_u32(smem);
    const int tid = threadIdx.x;
    const int wid = tid >> 5, lane = tid & 31;
    const int warpM = wid & 1, warpN = wid >> 1;
    const int row0 = blockIdx.y * 64;
    const int col0 = blockIdx.x * 128;
    const int KS = K >> 6;

    float acc[2][4][4];
#pragma unroll
    for (int i = 0; i < 2; i++)
#pragma unroll
        for (int j = 0; j < 4; j++)
#pragma unroll
            for (int t = 0; t < 4; t++) acc[i][j][t] = 0.f;

    auto prefetch = [&](int ks, int buf) {
        uint32_t sb = smu + (uint32_t)buf * GS_STAGE;
        int q = tid & 7;
        int rbase = tid >> 3;
        const __half* pA = A + (size_t)row0 * K + ks * 64;
        const __half* pB = B + (size_t)col0 * K + ks * 64;
#pragma unroll
        for (int i = 0; i < 2; i++) {            // 64 A rows
            int r = (i << 5) + rbase;
            const void* gp = pA + (size_t)r * K + q * 8;
            uint32_t sa = sb + sw128((uint32_t)(r * 128 + q * 16));
            asm volatile("cp.async.cg.shared.global [%0], [%1], 16;" :: "r"(sa), "l"(gp));
        }
#pragma unroll
        for (int i = 0; i < 4; i++) {            // 128 B rows
            int r = (i << 5) + rbase;
            const void* gp = pB + (size_t)r * K + q * 8;
            uint32_t sa = sb + 8192 + sw128((uint32_t)(r * 128 + q * 16));
            asm volatile("cp.async.cg.shared.global [%0], [%1], 16;" :: "r"(sa), "l"(gp));
        }
    };

    auto compute_k16 = [&](uint32_t sbase, int kk) {
        uint32_t ah[2][4], bh[2][4];
        int aRow = warpM * 32 + (lane & 15);
        int aK2 = (kk * 16 + ((lane & 16) ? 8 : 0)) * 2;
#pragma unroll
        for (int mt = 0; mt < 2; mt++) {
            uint32_t off = sw128((uint32_t)((aRow + mt * 16) * 128 + aK2));
            LDSM_X4(ah[mt][0], ah[mt][1], ah[mt][2], ah[mt][3], sbase + off);
        }
        int bRow = warpN * 32 + (lane & 7) + ((lane & 16) ? 8 : 0);
        int bK2 = (kk * 16 + ((lane & 8) ? 8 : 0)) * 2;
#pragma unroll
        for (int pr = 0; pr < 2; pr++) {
            uint32_t off = sw128((uint32_t)((bRow + pr * 16) * 128 + bK2));
            LDSM_X4(bh[pr][0], bh[pr][1], bh[pr][2], bh[pr][3], sbase + 8192 + off);
        }
#pragma unroll
        for (int mt = 0; mt < 2; mt++)
#pragma unroll
            for (int nt = 0; nt < 4; nt++)
                mma16816h(acc[mt][nt], ah[mt], &bh[nt >> 1][(nt & 1) * 2]);
    };

    prefetch(0, 0);
    asm volatile("cp.async.commit_group;" ::: "memory");
    prefetch(1, 1);
    asm volatile("cp.async.commit_group;" ::: "memory");
    prefetch(2, 2);
    asm volatile("cp.async.commit_group;" ::: "memory");

    int buf = 0;
    for (int ks = 0; ks < KS; ks++) {
        asm volatile("cp.async.wait_group 2;" ::: "memory");
        __syncthreads();
        uint32_t sbase = smu + (uint32_t)buf * GS_STAGE;
#pragma unroll
        for (int kk = 0; kk < 4; kk++) compute_k16(sbase, kk);
        __syncthreads();
        if (ks + 3 < KS) prefetch(ks + 3, buf);
        asm volatile("cp.async.commit_group;" ::: "memory");
        buf = (buf + 1 == 3) ? 0 : buf + 1;
    }

    int mBase = row0 + warpM * 32 + (lane >> 2);
    int nBase = col0 + warpN * 32 + (lane & 3) * 2;
#pragma unroll
    for (int mt = 0; mt < 2; mt++)
#pragma unroll
        for (int nt = 0; nt < 4; nt++) {
            int m = mBase + mt * 16;
            int n = nBase + nt * 8;
            if (OUT16) {
                float s = (n < 512) ? 0.125f : 1.0f;
                __half2 h0 = __floats2half2_rn(acc[mt][nt][0] * s, acc[mt][nt][1] * s);
                __half2 h1 = __floats2half2_rn(acc[mt][nt][2] * s, acc[mt][nt][3] * s);
                *(__half2*)(C16 + (size_t)m * N + n) = h0;
                *(__half2*)(C16 + (size_t)(m + 8) * N + n) = h1;
            } else {
                float2 v0 = make_float2(acc[mt][nt][0], acc[mt][nt][1]);
                float2 v1 = make_float2(acc[mt][nt][2], acc[mt][nt][3]);
                float b0 = bias[n], b1 = bias[n + 1];
                v0.x += b0; v0.y += b1; v1.x += b0; v1.y += b1;
                *(float2*)(C + (size_t)m * N + n) = v0;
                *(float2*)(C + (size_t)(m + 8) * N + n) = v1;
            }
        }
}

// ---------------- Fused pooling (levels 1..7, fp16 in/out, vectorized) -----
__device__ __forceinline__ void unpack8(uint4 u, float* f) {
    const uint32_t* w = &u.x;
#pragma unroll
    for (int i = 0; i < 4; i++) {
        float2 p = __half22float2(*(__half2*)&w[i]);
        f[i * 2] = p.x; f[i * 2 + 1] = p.y;
    }
}
__device__ __forceinline__ uint4 pack8(const float* f) {
    uint4 u;
    uint32_t* w = &u.x;
#pragma unroll
    for (int i = 0; i < 4; i++) {
        __half2 p = __floats2half2_rn(f[i * 2], f[i * 2 + 1]);
        w[i] = *(uint32_t*)&p;
    }
    return u;
}

__global__ __launch_bounds__(256)
void pool_fused(const __half* __restrict__ qkv)
{
    __shared__ float sA[64][192];
    __shared__ float sB[32][192];

    int c  = blockIdx.x;
    int bh = blockIdx.y;
    int b = bh >> 3, h = bh & 7;
    int tid = threadIdx.x;
    size_t poolbase = (size_t)bh * (POOLROWS * 64);

#pragma unroll
    for (int task = tid; task < 512; task += 256) {
        int li = task >> 3, dg = task & 7;
        size_t base = ((size_t)(b * 4096 + c * 128 + 2 * li)) * QKVW + h * 64 + dg * 8;
        float q0[8], q1[8], k0[8], k1[8], v0[8], v1[8];
        unpack8(*(const uint4*)(qkv + base), q0);
        unpack8(*(const uint4*)(qkv + base + QKVW), q1);
        unpack8(*(const uint4*)(qkv + base + 512), k0);
        unpack8(*(const uint4*)(qkv + base + 512 + QKVW), k1);
        unpack8(*(const uint4*)(qkv + base + 1024), v0);
        unpack8(*(const uint4*)(qkv + base + 1024 + QKVW), v1);
        float qo[8], ko[8], vo[8];
#pragma unroll
        for (int j = 0; j < 8; j++) {
            qo[j] = 0.5f * (q0[j] + q1[j]);
            ko[j] = 0.5f * (k0[j] + k1[j]);
            vo[j] = v0[j] + v1[j];
            sA[li][dg * 8 + j] = qo[j];
            sA[li][64 + dg * 8 + j] = ko[j];
            sA[li][128 + dg * 8 + j] = vo[j];
        }
        size_t dst = poolbase + (size_t)(c * 64 + li) * 64 + dg * 8;
        *(uint4*)(g_poolq + dst) = pack8(qo);
        *(uint4*)(g_poolk + dst) = pack8(ko);
        *(uint4*)(g_poolv + dst) = pack8(vo);
    }
    __syncthreads();

    for (int l = 2; l <= 7; l++) {
        int nl = 64 >> (l - 1);
        int offL = 4096 - (8192 >> l);
        bool srcA = (l & 1) == 0;
        for (int idx = tid; idx < nl * 64; idx += 256) {
            int i = idx >> 6, dd = idx & 63;
            float q0, q1, k0, k1, v0, v1;
            if (srcA) {
                q0 = sA[2 * i][dd];       q1 = sA[2 * i + 1][dd];
                k0 = sA[2 * i][64 + dd];  k1 = sA[2 * i + 1][64 + dd];
                v0 = sA[2 * i][128 + dd]; v1 = sA[2 * i + 1][128 + dd];
            } else {
                q0 = sB[2 * i][dd];       q1 = sB[2 * i + 1][dd];
                k0 = sB[2 * i][64 + dd];  k1 = sB[2 * i + 1][64 + dd];
                v0 = sB[2 * i][128 + dd]; v1 = sB[2 * i + 1][128 + dd];
            }
            float q = 0.5f * (q0 + q1);
            float k = 0.5f * (k0 + k1);
            float v = v0 + v1;
            if (srcA) { sB[i][dd] = q; sB[i][64 + dd] = k; sB[i][128 + dd] = v; }
            else      { sA[i][dd] = q; sA[i][64 + dd] = k; sA[i][128 + dd] = v; }
            size_t dst = poolbase + (size_t)(offL + c * nl + i) * 64 + dd;
            g_poolq[dst] = __float2half_rn(q);
            g_poolk[dst] = __float2half_rn(k);
            g_poolv[dst] = __float2half_rn(v);
        }
        __syncthreads();
    }
}

// ---------------- Shared attention core (per-warp 16x16 block) -------------
struct AttnOut {
    float y[8][4];
    float sr, sr8;
};

__device__ __forceinline__ void attn_block_core(
    const __half* qs, const __half* ks, const __half* vs, int stride,
    char* st, uint32_t su, int lane, AttnOut& o)
{
#pragma unroll
    for (int i = 0; i < 4; i++) {
        int chunk = i * 32 + lane;
        int row = chunk >> 3, qd = chunk & 7;
        uint32_t dst = sw128((uint32_t)(row * 128 + qd * 16));
        *(float4*)(st + dst)        = *(const float4*)(qs + (size_t)row * stride + qd * 8);
        *(float4*)(st + 2048 + dst) = *(const float4*)(ks + (size_t)row * stride + qd * 8);
        *(float4*)(st + 4096 + dst) = *(const float4*)(vs + (size_t)row * stride + qd * 8);
    }
    __syncwarp();

    float s[2][4];
#pragma unroll
    for (int j = 0; j < 2; j++)
#pragma unroll
        for (int t = 0; t < 4; t++) s[j][t] = 0.f;

    int aRow = lane & 15;
    int bRow = (lane & 7) + ((lane & 16) ? 8 : 0);
#pragma unroll
    for (int kk = 0; kk < 4; kk++) {
        uint32_t ah[4], bh[4];
        uint32_t aoff = sw128((uint32_t)(aRow * 128 + (kk * 16 + ((lane & 16) ? 8 : 0)) * 2));
        LDSM_X4(ah[0], ah[1], ah[2], ah[3], su + aoff);
        uint32_t boff = sw128((uint32_t)(bRow * 128 + (kk * 16 + ((lane & 8) ? 8 : 0)) * 2));
        LDSM_X4(bh[0], bh[1], bh[2], bh[3], su + 2048 + boff);
        mma16816h(s[0], ah, &bh[0]);
        mma16816h(s[1], ah, &bh[2]);
    }

    float e[2][4];
    uint32_t aF[4];
#pragma unroll
    for (int j = 0; j < 2; j++) {
#pragma unroll
        for (int t = 0; t < 4; t++) {
            __half hq = __float2half_rn(expf(s[j][t]));
            e[j][t] = __half2float(hq);
        }
        __half2 p0 = __floats2half2_rn(e[j][0], e[j][1]);
        __half2 p1 = __floats2half2_rn(e[j][2], e[j][3]);
        aF[j * 2 + 0] = *(uint32_t*)&p0;
        aF[j * 2 + 1] = *(uint32_t*)&p1;
    }

    float sr  = e[0][0] + e[0][1] + e[1][0] + e[1][1];
    float sr8 = e[0][2] + e[0][3] + e[1][2] + e[1][3];
    sr  += __shfl_xor_sync(0xffffffffu, sr, 1);
    sr  += __shfl_xor_sync(0xffffffffu, sr, 2);
    sr8 += __shfl_xor_sync(0xffffffffu, sr8, 1);
    sr8 += __shfl_xor_sync(0xffffffffu, sr8, 2);
    o.sr = sr; o.sr8 = sr8;

#pragma unroll
    for (int f = 0; f < 8; f++)
#pragma unroll
        for (int t = 0; t < 4; t++) o.y[f][t] = 0.f;

    int vRow = lane & 15;
    int vColBase = (lane & 16) ? 8 : 0;
#pragma unroll
    for (int vi = 0; vi < 4; vi++) {
        uint32_t vb[4];
        uint32_t voff = sw128((uint32_t)(vRow * 128 + (vColBase + vi * 16) * 2));
        LDSM_X4_T(vb[0], vb[1], vb[2], vb[3], su + 4096 + voff);
        mma16816h(o.y[vi * 2 + 0], aF, &vb[0]);
        mma16816h(o.y[vi * 2 + 1], aF, &vb[2]);
    }
}

// ---------------- attn over coarse levels (1..7) ---------------------------
__global__ __launch_bounds__(256)
void attn_coarse()
{
    __shared__ __align__(1024) char smem[8 * 6144];
    int warp = threadIdx.x >> 5;
    int lane = threadIdx.x & 31;
    int wg = blockIdx.x * 8 + warp;            // [0, 8128)

    int bh = wg / 254;
    int r  = wg - bh * 254;
    int level = 1, nb = 128;
    while (r >= nb) { r -= nb; nb >>= 1; level++; }
    int blk = r;
    int kblk = blk ^ 1;

    char* st = smem + warp * 6144;
    const uint32_t su = smem_to_u32(st);

    int off = 4096 - (8192 >> level);
    size_t pb = (size_t)bh * (POOLROWS * 64);
    const __half* qs = g_poolq + pb + (size_t)(off + blk * 16) * 64;
    const __half* ks = g_poolk + pb + (size_t)(off + kblk * 16) * 64;
    const __half* vs = g_poolv + pb + (size_t)(off + blk * 16) * 64;

    AttnOut o;
    attn_block_core(qs, ks, vs, 64, st, su, lane, o);

    int r0 = lane >> 2;
    int c0 = (lane & 3) * 2;
    __half* Ybase = g_Yc + pb + (size_t)(off + blk * 16) * 64;
#pragma unroll
    for (int f = 0; f < 8; f++) {
        int d0 = f * 8 + c0;
        *(__half2*)(Ybase + (size_t)r0 * 64 + d0)       = __floats2half2_rn(o.y[f][0], o.y[f][1]);
        *(__half2*)(Ybase + (size_t)(r0 + 8) * 64 + d0) = __floats2half2_rn(o.y[f][2], o.y[f][3]);
    }
    if ((lane & 3) == 0) {
        float* Ab = g_Ac + (size_t)bh * POOLROWS + off + blk * 16;
        Ab[r0] = o.sr;
        Ab[r0 + 8] = o.sr8;
    }
}

// ---------------- level-0 attention + inline coarse gather + combine -------
__global__ __launch_bounds__(256)
void attn0_combine(const __half* __restrict__ qkv)
{
    __shared__ __align__(1024) char smem[8 * 6144];
    int warp = threadIdx.x >> 5;
    int lane = threadIdx.x & 31;
    int wg = blockIdx.x * 8 + warp;            // [0, 8192)

    int bh = wg >> 8;
    int blk = wg & 255;
    int b = bh >> 3, h = bh & 7;

    char* st = smem + warp * 6144;
    const uint32_t su = smem_to_u32(st);

    size_t rq = (size_t)(b * 4096 + blk * 16) * QKVW;
    const __half* qs = qkv + rq + h * 64;
    const __half* ks = qkv + rq + 512 + h * 64;
    const __half* vs = qkv + rq + 1024 + h * 64;

    AttnOut o;
    attn_block_core(qs, ks, vs, QKVW, st, su, lane, o);

    // ---- gather coarse prefix (levels 1..7) into registers ----
    int n0 = blk * 16;
    int pbase = n0 >> 1;
    size_t pb = (size_t)bh * (POOLROWS * 64);
    const __half* Ycb = g_Yc + pb;
    const float* Acb = g_Ac + (size_t)bh * POOLROWS;

    int gr = lane >> 2;                 // this lane gathers prefix row gr (0..7)
    int gd = (lane & 3) * 16;           // 16 dims starting here
    float gacc[16];
#pragma unroll
    for (int i = 0; i < 16; i++) gacc[i] = 0.f;
    float ac = 0.f;
#pragma unroll
    for (int l = 1; l <= 7; l++) {
        int row = (4096 - (8192 >> l)) + ((pbase + gr) >> (l - 1));
        const __half* src = Ycb + (size_t)row * 64 + gd;
        float fa[8], fb[8];
        unpack8(*(const uint4*)(src), fa);
        unpack8(*(const uint4*)(src + 8), fb);
#pragma unroll
        for (int i = 0; i < 8; i++) { gacc[i] += fa[i]; gacc[8 + i] += fb[i]; }
        ac += Acb[row];
    }

    __syncwarp();                       // all smem reads in core done
    float* ys = (float*)st;             // 8 x 64 fp32 = 2048 B (reuse q region)
#pragma unroll
    for (int i = 0; i < 16; i++) ys[gr * 64 + gd + i] = gacc[i];
    __syncwarp();

    // ---- combine and emit fp16 att ----
    int r0 = lane >> 2;
    int c0 = (lane & 3) * 2;
    int p1 = r0 >> 1;
    int p2 = (r0 + 8) >> 1;
    float acA = __shfl_sync(0xffffffffu, ac, p1 * 4);
    float acB = __shfl_sync(0xffffffffu, ac, p2 * 4);
    float invA_r  = 1.f / (o.sr  + acA + 1e-8f);
    float invA_r8 = 1.f / (o.sr8 + acB + 1e-8f);

    __half* att_r  = g_atth + (size_t)(b * 4096 + n0 + r0) * 512 + h * 64;
    __half* att_r8 = g_atth + (size_t)(b * 4096 + n0 + r0 + 8) * 512 + h * 64;
#pragma unroll
    for (int f = 0; f < 8; f++) {
        int d0 = f * 8 + c0;
        float2 c_r  = *(float2*)&ys[p1 * 64 + d0];
        float2 c_r8 = *(float2*)&ys[p2 * 64 + d0];
        *(__half2*)(att_r + d0)  = __floats2half2_rn((o.y[f][0] + c_r.x) * invA_r,
                                                     (o.y[f][1] + c_r.y) * invA_r);
        *(__half2*)(att_r8 + d0) = __floats2half2_rn((o.y[f][2] + c_r8.x) * invA_r8,
                                                     (o.y[f][3] + c_r8.y) * invA_r8);
    }
}

// ---------------- Launch ----------------
extern "C" void kernel_launch(void* const* d_in, const int* in_sizes, int n_in,
                              void* d_out, int out_size)
{
    const float* x     = (const float*)d_in[0];
    const float* w_qkv = (const float*)d_in[1];
    const float* w_out = (const float*)d_in[2];
    const float* b_out = (const float*)d_in[3];
    float* out = (float*)d_out;

    __half *xh, *wqh, *woh, *ath, *qkv16;
    cudaGetSymbolAddress((void**)&xh, g_xh);
    cudaGetSymbolAddress((void**)&wqh, g_wqh);
    cudaGetSymbolAddress((void**)&woh, g_woh);
    cudaGetSymbolAddress((void**)&ath, g_atth);
    cudaGetSymbolAddress((void**)&qkv16, g_qkv16);

    cudaFuncSetAttribute(gemm_fp16<0>, cudaFuncAttributeMaxDynamicSharedMemorySize, GS_SMEM);
    cudaFuncSetAttribute(gemm_fp16<1>, cudaFuncAttributeMaxDynamicSharedMemorySize, GS_SMEM);

    // 1) Convert inputs to fp16
    convert_all<<<18432, 256>>>(x, w_qkv, w_out);

    // 2) QKV projection -> fp16 qkv (q pre-scaled 0.125)
    gemm_fp16<1><<<dim3(QKVW / 128, NROWS / 64), 256, GS_SMEM>>>(
        xh, wqh, nullptr, nullptr, qkv16, NROWS, QKVW, 1024);

    // 3) Fused pooling (fp16 planes, vectorized)
    pool_fused<<<dim3(32, 32), 256>>>(qkv16);

    // 4) Coarse attention (levels 1..7)
    attn_coarse<<<1016, 256>>>();

    // 5) Level-0 attention + inline coarse gather + combine -> fp16 att
    attn0_combine<<<1024, 256>>>(qkv16);

    // 6) Output projection (fp32 out + bias)
    gemm_fp16<0><<<dim3(1024 / 128, NROWS / 64), 256, GS_SMEM>>>(
        ath, woh, b_out, out, nullptr, NROWS, 1024, 512);
}

// round 14
// speedup vs baseline: 1.0165x; 1.0165x over previous
#include <cuda_runtime.h>
#include <cuda_fp16.h>
#include <cstdint>

// ---------------- Problem constants ----------------
#define NROWS   16384
#define QKVW    1536
#define POOLROWS 4064     // coarse rows per bh (levels 1..7)

// ---------------- Device scratch ----------------
__device__ __align__(16) __half g_Yc[(size_t)32 * POOLROWS * 64];   // coarse Y (levels 1..7)
__device__ __align__(16) float  g_Ac[(size_t)32 * POOLROWS];        // coarse Asum

__device__ __align__(16) __half g_qkv16[(size_t)NROWS * QKVW];
__device__ __align__(16) __half g_poolq[(size_t)32 * POOLROWS * 64];
__device__ __align__(16) __half g_poolk[(size_t)32 * POOLROWS * 64];
__device__ __align__(16) __half g_poolv[(size_t)32 * POOLROWS * 64];

__device__ __align__(16) __half g_xh[(size_t)NROWS * 1024];
__device__ __align__(16) __half g_wqh[(size_t)QKVW * 1024];
__device__ __align__(16) __half g_woh[(size_t)1024 * 512];
__device__ __align__(16) __half g_atth[(size_t)NROWS * 512];

// ---------------- helpers ----------------
__device__ __forceinline__ uint32_t smem_to_u32(const void* p) {
    uint32_t a;
    asm("{ .reg .u64 t; cvta.to.shared.u64 t, %1; cvt.u32.u64 %0, t; }" : "=r"(a) : "l"(p));
    return a;
}
__device__ __forceinline__ uint32_t sw128(uint32_t off) {
    return off ^ ((off >> 3) & 0x70);
}

#define LDSM_X4(r0, r1, r2, r3, addr) \
    asm volatile("ldmatrix.sync.aligned.m8n8.x4.shared.b16 {%0,%1,%2,%3}, [%4];" \
        : "=r"(r0), "=r"(r1), "=r"(r2), "=r"(r3) : "r"(addr))
#define LDSM_X4_T(r0, r1, r2, r3, addr) \
    asm volatile("ldmatrix.sync.aligned.m8n8.x4.trans.shared.b16 {%0,%1,%2,%3}, [%4];" \
        : "=r"(r0), "=r"(r1), "=r"(r2), "=r"(r3) : "r"(addr))

__device__ __forceinline__ void mma16816h(float* c, const uint32_t* a, const uint32_t* b) {
    asm volatile(
        "mma.sync.aligned.m16n8k16.row.col.f32.f16.f16.f32 "
        "{%0,%1,%2,%3}, {%4,%5,%6,%7}, {%8,%9}, {%0,%1,%2,%3};"
        : "+f"(c[0]), "+f"(c[1]), "+f"(c[2]), "+f"(c[3])
        : "r"(a[0]), "r"(a[1]), "r"(a[2]), "r"(a[3]), "r"(b[0]), "r"(b[1]));
}

__device__ __forceinline__ uint2 cvt4h(float4 v) {
    uint2 r;
    __half2 lo = __floats2half2_rn(v.x, v.y);
    __half2 hi = __floats2half2_rn(v.z, v.w);
    r.x = *(uint32_t*)&lo;
    r.y = *(uint32_t*)&hi;
    return r;
}

// ---------------- one-shot fp32 -> fp16 conversion (MLP=4) ----------------
// 4718592 quads total = 4608 blocks x 256 threads x 4 quads.
__global__ __launch_bounds__(256)
void convert_all(const float* __restrict__ x, const float* __restrict__ wq,
                 const float* __restrict__ wo)
{
    int base = (blockIdx.x * 256 + threadIdx.x) * 4;
    float4 v[4];
    uint2* dsts[4];
#pragma unroll
    for (int i = 0; i < 4; i++) {
        int q = base + i;
        const float* src;
        uint2* dst;
        int local;
        if (q < 4194304) {
            src = x; dst = (uint2*)g_xh; local = q;
        } else if (q < 4194304 + 393216) {
            src = wq; dst = (uint2*)g_wqh; local = q - 4194304;
        } else {
            src = wo; dst = (uint2*)g_woh; local = q - 4194304 - 393216;
        }
        v[i] = *(const float4*)(src + (size_t)local * 4);
        dsts[i] = dst + local;
    }
#pragma unroll
    for (int i = 0; i < 4; i++)
        *dsts[i] = cvt4h(v[i]);
}

// ---------------- fp16 GEMM (round-12 best: 128x128, BK=64, 2 CTAs/SM) ----
#define GS_STAGE 32768
#define GS_SMEM  (3 * GS_STAGE)

template <int OUT16>
__global__ __launch_bounds__(256, 2)
void gemm_fp16(const __half* __restrict__ A, const __half* __restrict__ B,
               const float* __restrict__ bias, float* __restrict__ C,
               __half* __restrict__ C16, int M, int N, int K)
{
    extern __shared__ __align__(1024) char smem[];
    const uint32_t smu = smem_to_u32(smem);
    const int tid = threadIdx.x;
    const int wid = tid >> 5, lane = tid & 31;
    const int warpM = wid & 1, warpN = wid >> 1;
    const int row0 = blockIdx.y * 128;
    const int col0 = blockIdx.x * 128;
    const int KS = K >> 6;

    float acc[4][4][4];
#pragma unroll
    for (int i = 0; i < 4; i++)
#pragma unroll
        for (int j = 0; j < 4; j++)
#pragma unroll
            for (int t = 0; t < 4; t++) acc[i][j][t] = 0.f;

    auto prefetch = [&](int ks, int buf) {
        uint32_t sb = smu + (uint32_t)buf * GS_STAGE;
        int q = tid & 7;
        int rbase = tid >> 3;
        const __half* pA = A + (size_t)row0 * K + ks * 64;
        const __half* pB = B + (size_t)col0 * K + ks * 64;
#pragma unroll
        for (int i = 0; i < 4; i++) {
            int r = (i << 5) + rbase;
            const void* gp = pA + (size_t)r * K + q * 8;
            uint32_t sa = sb + sw128((uint32_t)(r * 128 + q * 16));
            asm volatile("cp.async.cg.shared.global [%0], [%1], 16;" :: "r"(sa), "l"(gp));
        }
#pragma unroll
        for (int i = 0; i < 4; i++) {
            int r = (i << 5) + rbase;
            const void* gp = pB + (size_t)r * K + q * 8;
            uint32_t sa = sb + 16384 + sw128((uint32_t)(r * 128 + q * 16));
            asm volatile("cp.async.cg.shared.global [%0], [%1], 16;" :: "r"(sa), "l"(gp));
        }
    };

    auto compute_k16 = [&](uint32_t sbase, int kk) {
        uint32_t ah[4][4], bh[2][4];
        int aRow = warpM * 64 + (lane & 15);
        int aK2 = (kk * 16 + ((lane & 16) ? 8 : 0)) * 2;
#pragma unroll
        for (int mt = 0; mt < 4; mt++) {
            uint32_t off = sw128((uint32_t)((aRow + mt * 16) * 128 + aK2));
            LDSM_X4(ah[mt][0], ah[mt][1], ah[mt][2], ah[mt][3], sbase + off);
        }
        int bRow = warpN * 32 + (lane & 7) + ((lane & 16) ? 8 : 0);
        int bK2 = (kk * 16 + ((lane & 8) ? 8 : 0)) * 2;
#pragma unroll
        for (int pr = 0; pr < 2; pr++) {
            uint32_t off = sw128((uint32_t)((bRow + pr * 16) * 128 + bK2));
            LDSM_X4(bh[pr][0], bh[pr][1], bh[pr][2], bh[pr][3], sbase + 16384 + off);
        }
#pragma unroll
        for (int mt = 0; mt < 4; mt++)
#pragma unroll
            for (int nt = 0; nt < 4; nt++)
                mma16816h(acc[mt][nt], ah[mt], &bh[nt >> 1][(nt & 1) * 2]);
    };

    prefetch(0, 0);
    asm volatile("cp.async.commit_group;" ::: "memory");
    prefetch(1, 1);
    asm volatile("cp.async.commit_group;" ::: "memory");
    prefetch(2, 2);
    asm volatile("cp.async.commit_group;" ::: "memory");

    int buf = 0;
    for (int ks = 0; ks < KS; ks++) {
        asm volatile("cp.async.wait_group 2;" ::: "memory");
        __syncthreads();
        uint32_t sbase = smu + (uint32_t)buf * GS_STAGE;
#pragma unroll
        for (int kk = 0; kk < 4; kk++) compute_k16(sbase, kk);
        __syncthreads();
        if (ks + 3 < KS) prefetch(ks + 3, buf);
        asm volatile("cp.async.commit_group;" ::: "memory");
        buf = (buf + 1 == 3) ? 0 : buf + 1;
    }

    int mBase = row0 + warpM * 64 + (lane >> 2);
    int nBase = col0 + warpN * 32 + (lane & 3) * 2;
#pragma unroll
    for (int mt = 0; mt < 4; mt++)
#pragma unroll
        for (int nt = 0; nt < 4; nt++) {
            int m = mBase + mt * 16;
            int n = nBase + nt * 8;
            if (OUT16) {
                float s = (n < 512) ? 0.125f : 1.0f;
                __half2 h0 = __floats2half2_rn(acc[mt][nt][0] * s, acc[mt][nt][1] * s);
                __half2 h1 = __floats2half2_rn(acc[mt][nt][2] * s, acc[mt][nt][3] * s);
                *(__half2*)(C16 + (size_t)m * N + n) = h0;
                *(__half2*)(C16 + (size_t)(m + 8) * N + n) = h1;
            } else {
                float2 v0 = make_float2(acc[mt][nt][0], acc[mt][nt][1]);
                float2 v1 = make_float2(acc[mt][nt][2], acc[mt][nt][3]);
                float b0 = bias[n], b1 = bias[n + 1];
                v0.x += b0; v0.y += b1; v1.x += b0; v1.y += b1;
                *(float2*)(C + (size_t)m * N + n) = v0;
                *(float2*)(C + (size_t)(m + 8) * N + n) = v1;
            }
        }
}

// ---------------- Fused pooling (levels 1..7, fp16 in/out, vectorized) -----
__device__ __forceinline__ void unpack8(uint4 u, float* f) {
    const uint32_t* w = &u.x;
#pragma unroll
    for (int i = 0; i < 4; i++) {
        float2 p = __half22float2(*(__half2*)&w[i]);
        f[i * 2] = p.x; f[i * 2 + 1] = p.y;
    }
}
__device__ __forceinline__ uint4 pack8(const float* f) {
    uint4 u;
    uint32_t* w = &u.x;
#pragma unroll
    for (int i = 0; i < 4; i++) {
        __half2 p = __floats2half2_rn(f[i * 2], f[i * 2 + 1]);
        w[i] = *(uint32_t*)&p;
    }
    return u;
}

__global__ __launch_bounds__(256)
void pool_fused(const __half* __restrict__ qkv)
{
    __shared__ float sA[64][192];
    __shared__ float sB[32][192];

    int c  = blockIdx.x;
    int bh = blockIdx.y;
    int b = bh >> 3, h = bh & 7;
    int tid = threadIdx.x;
    size_t poolbase = (size_t)bh * (POOLROWS * 64);

#pragma unroll
    for (int task = tid; task < 512; task += 256) {
        int li = task >> 3, dg = task & 7;
        size_t base = ((size_t)(b * 4096 + c * 128 + 2 * li)) * QKVW + h * 64 + dg * 8;
        float q0[8], q1[8], k0[8], k1[8], v0[8], v1[8];
        unpack8(*(const uint4*)(qkv + base), q0);
        unpack8(*(const uint4*)(qkv + base + QKVW), q1);
        unpack8(*(const uint4*)(qkv + base + 512), k0);
        unpack8(*(const uint4*)(qkv + base + 512 + QKVW), k1);
        unpack8(*(const uint4*)(qkv + base + 1024), v0);
        unpack8(*(const uint4*)(qkv + base + 1024 + QKVW), v1);
        float qo[8], ko[8], vo[8];
#pragma unroll
        for (int j = 0; j < 8; j++) {
            qo[j] = 0.5f * (q0[j] + q1[j]);
            ko[j] = 0.5f * (k0[j] + k1[j]);
            vo[j] = v0[j] + v1[j];
            sA[li][dg * 8 + j] = qo[j];
            sA[li][64 + dg * 8 + j] = ko[j];
            sA[li][128 + dg * 8 + j] = vo[j];
        }
        size_t dst = poolbase + (size_t)(c * 64 + li) * 64 + dg * 8;
        *(uint4*)(g_poolq + dst) = pack8(qo);
        *(uint4*)(g_poolk + dst) = pack8(ko);
        *(uint4*)(g_poolv + dst) = pack8(vo);
    }
    __syncthreads();

    for (int l = 2; l <= 7; l++) {
        int nl = 64 >> (l - 1);
        int offL = 4096 - (8192 >> l);
        bool srcA = (l & 1) == 0;
        for (int idx = tid; idx < nl * 64; idx += 256) {
            int i = idx >> 6, dd = idx & 63;
            float q0, q1, k0, k1, v0, v1;
            if (srcA) {
                q0 = sA[2 * i][dd];       q1 = sA[2 * i + 1][dd];
                k0 = sA[2 * i][64 + dd];  k1 = sA[2 * i + 1][64 + dd];
                v0 = sA[2 * i][128 + dd]; v1 = sA[2 * i + 1][128 + dd];
            } else {
                q0 = sB[2 * i][dd];       q1 = sB[2 * i + 1][dd];
                k0 = sB[2 * i][64 + dd];  k1 = sB[2 * i + 1][64 + dd];
                v0 = sB[2 * i][128 + dd]; v1 = sB[2 * i + 1][128 + dd];
            }
            float q = 0.5f * (q0 + q1);
            float k = 0.5f * (k0 + k1);
            float v = v0 + v1;
            if (srcA) { sB[i][dd] = q; sB[i][64 + dd] = k; sB[i][128 + dd] = v; }
            else      { sA[i][dd] = q; sA[i][64 + dd] = k; sA[i][128 + dd] = v; }
            size_t dst = poolbase + (size_t)(offL + c * nl + i) * 64 + dd;
            g_poolq[dst] = __float2half_rn(q);
            g_poolk[dst] = __float2half_rn(k);
            g_poolv[dst] = __float2half_rn(v);
        }
        __syncthreads();
    }
}

// ---------------- Shared attention core (per-warp 16x16 block) -------------
struct AttnOut {
    float y[8][4];
    float sr, sr8;
};

__device__ __forceinline__ void attn_block_core(
    const __half* qs, const __half* ks, const __half* vs, int stride,
    char* st, uint32_t su, int lane, AttnOut& o)
{
#pragma unroll
    for (int i = 0; i < 4; i++) {
        int chunk = i * 32 + lane;
        int row = chunk >> 3, qd = chunk & 7;
        uint32_t dst = sw128((uint32_t)(row * 128 + qd * 16));
        *(float4*)(st + dst)        = *(const float4*)(qs + (size_t)row * stride + qd * 8);
        *(float4*)(st + 2048 + dst) = *(const float4*)(ks + (size_t)row * stride + qd * 8);
        *(float4*)(st + 4096 + dst) = *(const float4*)(vs + (size_t)row * stride + qd * 8);
    }
    __syncwarp();

    float s[2][4];
#pragma unroll
    for (int j = 0; j < 2; j++)
#pragma unroll
        for (int t = 0; t < 4; t++) s[j][t] = 0.f;

    int aRow = lane & 15;
    int bRow = (lane & 7) + ((lane & 16) ? 8 : 0);
#pragma unroll
    for (int kk = 0; kk < 4; kk++) {
        uint32_t ah[4], bh[4];
        uint32_t aoff = sw128((uint32_t)(aRow * 128 + (kk * 16 + ((lane & 16) ? 8 : 0)) * 2));
        LDSM_X4(ah[0], ah[1], ah[2], ah[3], su + aoff);
        uint32_t boff = sw128((uint32_t)(bRow * 128 + (kk * 16 + ((lane & 8) ? 8 : 0)) * 2));
        LDSM_X4(bh[0], bh[1], bh[2], bh[3], su + 2048 + boff);
        mma16816h(s[0], ah, &bh[0]);
        mma16816h(s[1], ah, &bh[2]);
    }

    float e[2][4];
    uint32_t aF[4];
#pragma unroll
    for (int j = 0; j < 2; j++) {
#pragma unroll
        for (int t = 0; t < 4; t++) {
            __half hq = __float2half_rn(expf(s[j][t]));
            e[j][t] = __half2float(hq);
        }
        __half2 p0 = __floats2half2_rn(e[j][0], e[j][1]);
        __half2 p1 = __floats2half2_rn(e[j][2], e[j][3]);
        aF[j * 2 + 0] = *(uint32_t*)&p0;
        aF[j * 2 + 1] = *(uint32_t*)&p1;
    }

    float sr  = e[0][0] + e[0][1] + e[1][0] + e[1][1];
    float sr8 = e[0][2] + e[0][3] + e[1][2] + e[1][3];
    sr  += __shfl_xor_sync(0xffffffffu, sr, 1);
    sr  += __shfl_xor_sync(0xffffffffu, sr, 2);
    sr8 += __shfl_xor_sync(0xffffffffu, sr8, 1);
    sr8 += __shfl_xor_sync(0xffffffffu, sr8, 2);
    o.sr = sr; o.sr8 = sr8;

#pragma unroll
    for (int f = 0; f < 8; f++)
#pragma unroll
        for (int t = 0; t < 4; t++) o.y[f][t] = 0.f;

    int vRow = lane & 15;
    int vColBase = (lane & 16) ? 8 : 0;
#pragma unroll
    for (int vi = 0; vi < 4; vi++) {
        uint32_t vb[4];
        uint32_t voff = sw128((uint32_t)(vRow * 128 + (vColBase + vi * 16) * 2));
        LDSM_X4_T(vb[0], vb[1], vb[2], vb[3], su + 4096 + voff);
        mma16816h(o.y[vi * 2 + 0], aF, &vb[0]);
        mma16816h(o.y[vi * 2 + 1], aF, &vb[2]);
    }
}

// ---------------- attn over coarse levels (1..7) ---------------------------
__global__ __launch_bounds__(256)
void attn_coarse()
{
    __shared__ __align__(1024) char smem[8 * 6144];
    int warp = threadIdx.x >> 5;
    int lane = threadIdx.x & 31;
    int wg = blockIdx.x * 8 + warp;            // [0, 8128)

    int bh = wg / 254;
    int r  = wg - bh * 254;
    int level = 1, nb = 128;
    while (r >= nb) { r -= nb; nb >>= 1; level++; }
    int blk = r;
    int kblk = blk ^ 1;

    char* st = smem + warp * 6144;
    const uint32_t su = smem_to_u32(st);

    int off = 4096 - (8192 >> level);
    size_t pb = (size_t)bh * (POOLROWS * 64);
    const __half* qs = g_poolq + pb + (size_t)(off + blk * 16) * 64;
    const __half* ks = g_poolk + pb + (size_t)(off + kblk * 16) * 64;
    const __half* vs = g_poolv + pb + (size_t)(off + blk * 16) * 64;

    AttnOut o;
    attn_block_core(qs, ks, vs, 64, st, su, lane, o);

    int r0 = lane >> 2;
    int c0 = (lane & 3) * 2;
    __half* Ybase = g_Yc + pb + (size_t)(off + blk * 16) * 64;
#pragma unroll
    for (int f = 0; f < 8; f++) {
        int d0 = f * 8 + c0;
        *(__half2*)(Ybase + (size_t)r0 * 64 + d0)       = __floats2half2_rn(o.y[f][0], o.y[f][1]);
        *(__half2*)(Ybase + (size_t)(r0 + 8) * 64 + d0) = __floats2half2_rn(o.y[f][2], o.y[f][3]);
    }
    if ((lane & 3) == 0) {
        float* Ab = g_Ac + (size_t)bh * POOLROWS + off + blk * 16;
        Ab[r0] = o.sr;
        Ab[r0 + 8] = o.sr8;
    }
}

// ---------------- level-0 attention + inline coarse gather + combine -------
__global__ __launch_bounds__(256)
void attn0_combine(const __half* __restrict__ qkv)
{
    __shared__ __align__(1024) char smem[8 * 6144];
    int warp = threadIdx.x >> 5;
    int lane = threadIdx.x & 31;
    int wg = blockIdx.x * 8 + warp;            // [0, 8192)

    int bh = wg >> 8;
    int blk = wg & 255;
    int b = bh >> 3, h = bh & 7;

    char* st = smem + warp * 6144;
    const uint32_t su = smem_to_u32(st);

    size_t rq = (size_t)(b * 4096 + blk * 16) * QKVW;
    const __half* qs = qkv + rq + h * 64;
    const __half* ks = qkv + rq + 512 + h * 64;
    const __half* vs = qkv + rq + 1024 + h * 64;

    AttnOut o;
    attn_block_core(qs, ks, vs, QKVW, st, su, lane, o);

    // ---- gather coarse prefix (levels 1..7) into registers ----
    int n0 = blk * 16;
    int pbase = n0 >> 1;
    size_t pb = (size_t)bh * (POOLROWS * 64);
    const __half* Ycb = g_Yc + pb;
    const float* Acb = g_Ac + (size_t)bh * POOLROWS;

    int gr = lane >> 2;                 // this lane gathers prefix row gr (0..7)
    int gd = (lane & 3) * 16;           // 16 dims starting here
    float gacc[16];
#pragma unroll
    for (int i = 0; i < 16; i++) gacc[i] = 0.f;
    float ac = 0.f;
#pragma unroll
    for (int l = 1; l <= 7; l++) {
        int row = (4096 - (8192 >> l)) + ((pbase + gr) >> (l - 1));
        const __half* src = Ycb + (size_t)row * 64 + gd;
        float fa[8], fb[8];
        unpack8(*(const uint4*)(src), fa);
        unpack8(*(const uint4*)(src + 8), fb);
#pragma unroll
        for (int i = 0; i < 8; i++) { gacc[i] += fa[i]; gacc[8 + i] += fb[i]; }
        ac += Acb[row];
    }

    __syncwarp();                       // all smem reads in core done
    float* ys = (float*)st;             // 8 x 64 fp32 = 2048 B (reuse q region)
#pragma unroll
    for (int i = 0; i < 16; i++) ys[gr * 64 + gd + i] = gacc[i];
    __syncwarp();

    // ---- combine and emit fp16 att ----
    int r0 = lane >> 2;
    int c0 = (lane & 3) * 2;
    int p1 = r0 >> 1;
    int p2 = (r0 + 8) >> 1;
    float acA = __shfl_sync(0xffffffffu, ac, p1 * 4);
    float acB = __shfl_sync(0xffffffffu, ac, p2 * 4);
    float invA_r  = 1.f / (o.sr  + acA + 1e-8f);
    float invA_r8 = 1.f / (o.sr8 + acB + 1e-8f);

    __half* att_r  = g_atth + (size_t)(b * 4096 + n0 + r0) * 512 + h * 64;
    __half* att_r8 = g_atth + (size_t)(b * 4096 + n0 + r0 + 8) * 512 + h * 64;
#pragma unroll
    for (int f = 0; f < 8; f++) {
        int d0 = f * 8 + c0;
        float2 c_r  = *(float2*)&ys[p1 * 64 + d0];
        float2 c_r8 = *(float2*)&ys[p2 * 64 + d0];
        *(__half2*)(att_r + d0)  = __floats2half2_rn((o.y[f][0] + c_r.x) * invA_r,
                                                     (o.y[f][1] + c_r.y) * invA_r);
        *(__half2*)(att_r8 + d0) = __floats2half2_rn((o.y[f][2] + c_r8.x) * invA_r8,
                                                     (o.y[f][3] + c_r8.y) * invA_r8);
    }
}

// ---------------- Launch ----------------
extern "C" void kernel_launch(void* const* d_in, const int* in_sizes, int n_in,
                              void* d_out, int out_size)
{
    const float* x     = (const float*)d_in[0];
    const float* w_qkv = (const float*)d_in[1];
    const float* w_out = (const float*)d_in[2];
    const float* b_out = (const float*)d_in[3];
    float* out = (float*)d_out;

    __half *xh, *wqh, *woh, *ath, *qkv16;
    cudaGetSymbolAddress((void**)&xh, g_xh);
    cudaGetSymbolAddress((void**)&wqh, g_wqh);
    cudaGetSymbolAddress((void**)&woh, g_woh);
    cudaGetSymbolAddress((void**)&ath, g_atth);
    cudaGetSymbolAddress((void**)&qkv16, g_qkv16);

    cudaFuncSetAttribute(gemm_fp16<0>, cudaFuncAttributeMaxDynamicSharedMemorySize, GS_SMEM);
    cudaFuncSetAttribute(gemm_fp16<1>, cudaFuncAttributeMaxDynamicSharedMemorySize, GS_SMEM);

    // 1) Convert inputs to fp16 (MLP=4)
    convert_all<<<4608, 256>>>(x, w_qkv, w_out);

    // 2) QKV projection -> fp16 qkv (q pre-scaled 0.125)
    gemm_fp16<1><<<dim3(QKVW / 128, NROWS / 128), 256, GS_SMEM>>>(
        xh, wqh, nullptr, nullptr, qkv16, NROWS, QKVW, 1024);

    // 3) Fused pooling (fp16 planes, vectorized)
    pool_fused<<<dim3(32, 32), 256>>>(qkv16);

    // 4) Coarse attention (levels 1..7)
    attn_coarse<<<1016, 256>>>();

    // 5) Level-0 attention + inline coarse gather + combine -> fp16 att
    attn0_combine<<<1024, 256>>>(qkv16);

    // 6) Output projection (fp32 out + bias)
    gemm_fp16<0><<<dim3(1024 / 128, NROWS / 128), 256, GS_SMEM>>>(
        ath, woh, b_out, out, nullptr, NROWS, 1024, 512);
}

// round 15
// speedup vs baseline: 1.0251x; 1.0084x over previous
#include <cuda_runtime.h>
#include <cuda_fp16.h>
#include <cstdint>

// ---------------- Problem constants ----------------
#define NROWS   16384
#define QKVW    1536
#define POOLROWS 4064     // coarse rows per bh (levels 1..7)

// ---------------- Device scratch ----------------
__device__ __align__(16) __half g_Yc[(size_t)32 * POOLROWS * 64];   // coarse Y (levels 1..7)
__device__ __align__(16) float  g_Ac[(size_t)32 * POOLROWS];        // coarse Asum

__device__ __align__(16) __half g_qkv16[(size_t)NROWS * QKVW];
__device__ __align__(16) __half g_poolq[(size_t)32 * POOLROWS * 64];
__device__ __align__(16) __half g_poolk[(size_t)32 * POOLROWS * 64];
__device__ __align__(16) __half g_poolv[(size_t)32 * POOLROWS * 64];

__device__ __align__(16) __half g_xh[(size_t)NROWS * 1024];
__device__ __align__(16) __half g_wqh[(size_t)QKVW * 1024];
__device__ __align__(16) __half g_woh[(size_t)1024 * 512];
__device__ __align__(16) __half g_atth[(size_t)NROWS * 512];

// ---------------- helpers ----------------
__device__ __forceinline__ uint32_t smem_to_u32(const void* p) {
    uint32_t a;
    asm("{ .reg .u64 t; cvta.to.shared.u64 t, %1; cvt.u32.u64 %0, t; }" : "=r"(a) : "l"(p));
    return a;
}
__device__ __forceinline__ uint32_t sw128(uint32_t off) {
    return off ^ ((off >> 3) & 0x70);
}

#define LDSM_X4(r0, r1, r2, r3, addr) \
    asm volatile("ldmatrix.sync.aligned.m8n8.x4.shared.b16 {%0,%1,%2,%3}, [%4];" \
        : "=r"(r0), "=r"(r1), "=r"(r2), "=r"(r3) : "r"(addr))
#define LDSM_X4_T(r0, r1, r2, r3, addr) \
    asm volatile("ldmatrix.sync.aligned.m8n8.x4.trans.shared.b16 {%0,%1,%2,%3}, [%4];" \
        : "=r"(r0), "=r"(r1), "=r"(r2), "=r"(r3) : "r"(addr))

__device__ __forceinline__ void mma16816h(float* c, const uint32_t* a, const uint32_t* b) {
    asm volatile(
        "mma.sync.aligned.m16n8k16.row.col.f32.f16.f16.f32 "
        "{%0,%1,%2,%3}, {%4,%5,%6,%7}, {%8,%9}, {%0,%1,%2,%3};"
        : "+f"(c[0]), "+f"(c[1]), "+f"(c[2]), "+f"(c[3])
        : "r"(a[0]), "r"(a[1]), "r"(a[2]), "r"(a[3]), "r"(b[0]), "r"(b[1]));
}

__device__ __forceinline__ uint2 cvt4h(float4 v) {
    uint2 r;
    __half2 lo = __floats2half2_rn(v.x, v.y);
    __half2 hi = __floats2half2_rn(v.z, v.w);
    r.x = *(uint32_t*)&lo;
    r.y = *(uint32_t*)&hi;
    return r;
}

// ---------------- one-shot fp32 -> fp16 conversion ----------------
__global__ __launch_bounds__(256)
void convert_all(const float* __restrict__ x, const float* __restrict__ wq,
                 const float* __restrict__ wo)
{
    int q = blockIdx.x * 256 + threadIdx.x;
    const float* src;
    uint2* dst;
    int local;
    if (q < 4194304) {
        src = x; dst = (uint2*)g_xh; local = q;
    } else if (q < 4194304 + 393216) {
        src = wq; dst = (uint2*)g_wqh; local = q - 4194304;
    } else {
        src = wo; dst = (uint2*)g_woh; local = q - 4194304 - 393216;
    }
    float4 v = *(const float4*)(src + (size_t)local * 4);
    dst[local] = cvt4h(v);
}

// ---------------- fp16 GEMM (128x128, BK=64, 2 CTAs/SM, 3-stage) ----------
#define GS_STAGE 32768
#define GS_SMEM  (3 * GS_STAGE)

template <int OUT16>
__global__ __launch_bounds__(256, 2)
void gemm_fp16(const __half* __restrict__ A, const __half* __restrict__ B,
               const float* __restrict__ bias, float* __restrict__ C,
               __half* __restrict__ C16, int M, int N, int K)
{
    extern __shared__ __align__(1024) char smem[];
    const uint32_t smu = smem_to_u32(smem);
    const int tid = threadIdx.x;
    const int wid = tid >> 5, lane = tid & 31;
    const int warpM = wid & 1, warpN = wid >> 1;
    const int row0 = blockIdx.y * 128;
    const int col0 = blockIdx.x * 128;
    const int KS = K >> 6;

    float acc[4][4][4];
#pragma unroll
    for (int i = 0; i < 4; i++)
#pragma unroll
        for (int j = 0; j < 4; j++)
#pragma unroll
            for (int t = 0; t < 4; t++) acc[i][j][t] = 0.f;

    auto prefetch = [&](int ks, int buf) {
        uint32_t sb = smu + (uint32_t)buf * GS_STAGE;
        int q = tid & 7;
        int rbase = tid >> 3;
        const __half* pA = A + (size_t)row0 * K + ks * 64;
        const __half* pB = B + (size_t)col0 * K + ks * 64;
#pragma unroll
        for (int i = 0; i < 4; i++) {
            int r = (i << 5) + rbase;
            const void* gp = pA + (size_t)r * K + q * 8;
            uint32_t sa = sb + sw128((uint32_t)(r * 128 + q * 16));
            asm volatile("cp.async.cg.shared.global [%0], [%1], 16;" :: "r"(sa), "l"(gp));
        }
#pragma unroll
        for (int i = 0; i < 4; i++) {
            int r = (i << 5) + rbase;
            const void* gp = pB + (size_t)r * K + q * 8;
            uint32_t sa = sb + 16384 + sw128((uint32_t)(r * 128 + q * 16));
            asm volatile("cp.async.cg.shared.global [%0], [%1], 16;" :: "r"(sa), "l"(gp));
        }
    };

    auto compute_k16 = [&](uint32_t sbase, int kk) {
        uint32_t ah[4][4], bh[2][4];
        int aRow = warpM * 64 + (lane & 15);
        int aK2 = (kk * 16 + ((lane & 16) ? 8 : 0)) * 2;
#pragma unroll
        for (int mt = 0; mt < 4; mt++) {
            uint32_t off = sw128((uint32_t)((aRow + mt * 16) * 128 + aK2));
            LDSM_X4(ah[mt][0], ah[mt][1], ah[mt][2], ah[mt][3], sbase + off);
        }
        int bRow = warpN * 32 + (lane & 7) + ((lane & 16) ? 8 : 0);
        int bK2 = (kk * 16 + ((lane & 8) ? 8 : 0)) * 2;
#pragma unroll
        for (int pr = 0; pr < 2; pr++) {
            uint32_t off = sw128((uint32_t)((bRow + pr * 16) * 128 + bK2));
            LDSM_X4(bh[pr][0], bh[pr][1], bh[pr][2], bh[pr][3], sbase + 16384 + off);
        }
#pragma unroll
        for (int mt = 0; mt < 4; mt++)
#pragma unroll
            for (int nt = 0; nt < 4; nt++)
                mma16816h(acc[mt][nt], ah[mt], &bh[nt >> 1][(nt & 1) * 2]);
    };

    prefetch(0, 0);
    asm volatile("cp.async.commit_group;" ::: "memory");
    prefetch(1, 1);
    asm volatile("cp.async.commit_group;" ::: "memory");
    prefetch(2, 2);
    asm volatile("cp.async.commit_group;" ::: "memory");

    int buf = 0;
    for (int ks = 0; ks < KS; ks++) {
        asm volatile("cp.async.wait_group 2;" ::: "memory");
        __syncthreads();
        uint32_t sbase = smu + (uint32_t)buf * GS_STAGE;
#pragma unroll
        for (int kk = 0; kk < 4; kk++) compute_k16(sbase, kk);
        __syncthreads();
        if (ks + 3 < KS) prefetch(ks + 3, buf);
        asm volatile("cp.async.commit_group;" ::: "memory");
        buf = (buf + 1 == 3) ? 0 : buf + 1;
    }

    int mBase = row0 + warpM * 64 + (lane >> 2);
    int nBase = col0 + warpN * 32 + (lane & 3) * 2;
#pragma unroll
    for (int mt = 0; mt < 4; mt++)
#pragma unroll
        for (int nt = 0; nt < 4; nt++) {
            int m = mBase + mt * 16;
            int n = nBase + nt * 8;
            if (OUT16) {
                float s = (n < 512) ? 0.125f : 1.0f;
                __half2 h0 = __floats2half2_rn(acc[mt][nt][0] * s, acc[mt][nt][1] * s);
                __half2 h1 = __floats2half2_rn(acc[mt][nt][2] * s, acc[mt][nt][3] * s);
                *(__half2*)(C16 + (size_t)m * N + n) = h0;
                *(__half2*)(C16 + (size_t)(m + 8) * N + n) = h1;
            } else {
                float2 v0 = make_float2(acc[mt][nt][0], acc[mt][nt][1]);
                float2 v1 = make_float2(acc[mt][nt][2], acc[mt][nt][3]);
                float b0 = bias[n], b1 = bias[n + 1];
                v0.x += b0; v0.y += b1; v1.x += b0; v1.y += b1;
                *(float2*)(C + (size_t)m * N + n) = v0;
                *(float2*)(C + (size_t)(m + 8) * N + n) = v1;
            }
        }
}

// ---------------- Fused pooling (levels 1..7, fp16 in/out, vectorized) -----
__device__ __forceinline__ void unpack8(uint4 u, float* f) {
    const uint32_t* w = &u.x;
#pragma unroll
    for (int i = 0; i < 4; i++) {
        float2 p = __half22float2(*(__half2*)&w[i]);
        f[i * 2] = p.x; f[i * 2 + 1] = p.y;
    }
}
__device__ __forceinline__ uint4 pack8(const float* f) {
    uint4 u;
    uint32_t* w = &u.x;
#pragma unroll
    for (int i = 0; i < 4; i++) {
        __half2 p = __floats2half2_rn(f[i * 2], f[i * 2 + 1]);
        w[i] = *(uint32_t*)&p;
    }
    return u;
}

__global__ __launch_bounds__(256)
void pool_fused(const __half* __restrict__ qkv)
{
    __shared__ float sA[64][192];
    __shared__ float sB[32][192];

    int c  = blockIdx.x;
    int bh = blockIdx.y;
    int b = bh >> 3, h = bh & 7;
    int tid = threadIdx.x;
    size_t poolbase = (size_t)bh * (POOLROWS * 64);

#pragma unroll
    for (int task = tid; task < 512; task += 256) {
        int li = task >> 3, dg = task & 7;
        size_t base = ((size_t)(b * 4096 + c * 128 + 2 * li)) * QKVW + h * 64 + dg * 8;
        float q0[8], q1[8], k0[8], k1[8], v0[8], v1[8];
        unpack8(*(const uint4*)(qkv + base), q0);
        unpack8(*(const uint4*)(qkv + base + QKVW), q1);
        unpack8(*(const uint4*)(qkv + base + 512), k0);
        unpack8(*(const uint4*)(qkv + base + 512 + QKVW), k1);
        unpack8(*(const uint4*)(qkv + base + 1024), v0);
        unpack8(*(const uint4*)(qkv + base + 1024 + QKVW), v1);
        float qo[8], ko[8], vo[8];
#pragma unroll
        for (int j = 0; j < 8; j++) {
            qo[j] = 0.5f * (q0[j] + q1[j]);
            ko[j] = 0.5f * (k0[j] + k1[j]);
            vo[j] = v0[j] + v1[j];
            sA[li][dg * 8 + j] = qo[j];
            sA[li][64 + dg * 8 + j] = ko[j];
            sA[li][128 + dg * 8 + j] = vo[j];
        }
        size_t dst = poolbase + (size_t)(c * 64 + li) * 64 + dg * 8;
        *(uint4*)(g_poolq + dst) = pack8(qo);
        *(uint4*)(g_poolk + dst) = pack8(ko);
        *(uint4*)(g_poolv + dst) = pack8(vo);
    }
    __syncthreads();

    for (int l = 2; l <= 7; l++) {
        int nl = 64 >> (l - 1);
        int offL = 4096 - (8192 >> l);
        bool srcA = (l & 1) == 0;
        for (int idx = tid; idx < nl * 64; idx += 256) {
            int i = idx >> 6, dd = idx & 63;
            float q0, q1, k0, k1, v0, v1;
            if (srcA) {
                q0 = sA[2 * i][dd];       q1 = sA[2 * i + 1][dd];
                k0 = sA[2 * i][64 + dd];  k1 = sA[2 * i + 1][64 + dd];
                v0 = sA[2 * i][128 + dd]; v1 = sA[2 * i + 1][128 + dd];
            } else {
                q0 = sB[2 * i][dd];       q1 = sB[2 * i + 1][dd];
                k0 = sB[2 * i][64 + dd];  k1 = sB[2 * i + 1][64 + dd];
                v0 = sB[2 * i][128 + dd]; v1 = sB[2 * i + 1][128 + dd];
            }
            float q = 0.5f * (q0 + q1);
            float k = 0.5f * (k0 + k1);
            float v = v0 + v1;
            if (srcA) { sB[i][dd] = q; sB[i][64 + dd] = k; sB[i][128 + dd] = v; }
            else      { sA[i][dd] = q; sA[i][64 + dd] = k; sA[i][128 + dd] = v; }
            size_t dst = poolbase + (size_t)(offL + c * nl + i) * 64 + dd;
            g_poolq[dst] = __float2half_rn(q);
            g_poolk[dst] = __float2half_rn(k);
            g_poolv[dst] = __float2half_rn(v);
        }
        __syncthreads();
    }
}

// ---------------- Shared attention core (per-warp 16x16 block) -------------
struct AttnOut {
    float y[8][4];
    float sr, sr8;
};

__device__ __forceinline__ void attn_block_core(
    const __half* qs, const __half* ks, const __half* vs, int stride,
    char* st, uint32_t su, int lane, AttnOut& o)
{
#pragma unroll
    for (int i = 0; i < 4; i++) {
        int chunk = i * 32 + lane;
        int row = chunk >> 3, qd = chunk & 7;
        uint32_t dst = sw128((uint32_t)(row * 128 + qd * 16));
        *(float4*)(st + dst)        = *(const float4*)(qs + (size_t)row * stride + qd * 8);
        *(float4*)(st + 2048 + dst) = *(const float4*)(ks + (size_t)row * stride + qd * 8);
        *(float4*)(st + 4096 + dst) = *(const float4*)(vs + (size_t)row * stride + qd * 8);
    }
    __syncwarp();

    float s[2][4];
#pragma unroll
    for (int j = 0; j < 2; j++)
#pragma unroll
        for (int t = 0; t < 4; t++) s[j][t] = 0.f;

    int aRow = lane & 15;
    int bRow = (lane & 7) + ((lane & 16) ? 8 : 0);
#pragma unroll
    for (int kk = 0; kk < 4; kk++) {
        uint32_t ah[4], bh[4];
        uint32_t aoff = sw128((uint32_t)(aRow * 128 + (kk * 16 + ((lane & 16) ? 8 : 0)) * 2));
        LDSM_X4(ah[0], ah[1], ah[2], ah[3], su + aoff);
        uint32_t boff = sw128((uint32_t)(bRow * 128 + (kk * 16 + ((lane & 8) ? 8 : 0)) * 2));
        LDSM_X4(bh[0], bh[1], bh[2], bh[3], su + 2048 + boff);
        mma16816h(s[0], ah, &bh[0]);
        mma16816h(s[1], ah, &bh[2]);
    }

    // fast exp (MUFU EX2 path), quantize A to fp16; same values feed asum.
    float e[2][4];
    uint32_t aF[4];
#pragma unroll
    for (int j = 0; j < 2; j++) {
#pragma unroll
        for (int t = 0; t < 4; t++) {
            __half hq = __float2half_rn(__expf(s[j][t]));
            e[j][t] = __half2float(hq);
        }
        __half2 p0 = __floats2half2_rn(e[j][0], e[j][1]);
        __half2 p1 = __floats2half2_rn(e[j][2], e[j][3]);
        aF[j * 2 + 0] = *(uint32_t*)&p0;
        aF[j * 2 + 1] = *(uint32_t*)&p1;
    }

    float sr  = e[0][0] + e[0][1] + e[1][0] + e[1][1];
    float sr8 = e[0][2] + e[0][3] + e[1][2] + e[1][3];
    sr  += __shfl_xor_sync(0xffffffffu, sr, 1);
    sr  += __shfl_xor_sync(0xffffffffu, sr, 2);
    sr8 += __shfl_xor_sync(0xffffffffu, sr8, 1);
    sr8 += __shfl_xor_sync(0xffffffffu, sr8, 2);
    o.sr = sr; o.sr8 = sr8;

#pragma unroll
    for (int f = 0; f < 8; f++)
#pragma unroll
        for (int t = 0; t < 4; t++) o.y[f][t] = 0.f;

    int vRow = lane & 15;
    int vColBase = (lane & 16) ? 8 : 0;
#pragma unroll
    for (int vi = 0; vi < 4; vi++) {
        uint32_t vb[4];
        uint32_t voff = sw128((uint32_t)(vRow * 128 + (vColBase + vi * 16) * 2));
        LDSM_X4_T(vb[0], vb[1], vb[2], vb[3], su + 4096 + voff);
        mma16816h(o.y[vi * 2 + 0], aF, &vb[0]);
        mma16816h(o.y[vi * 2 + 1], aF, &vb[2]);
    }
}

// ---------------- attn over coarse levels (1..7) ---------------------------
__global__ __launch_bounds__(256)
void attn_coarse()
{
    __shared__ __align__(1024) char smem[8 * 6144];
    int warp = threadIdx.x >> 5;
    int lane = threadIdx.x & 31;
    int wg = blockIdx.x * 8 + warp;            // [0, 8128)

    int bh = wg / 254;
    int r  = wg - bh * 254;
    int level = 1, nb = 128;
    while (r >= nb) { r -= nb; nb >>= 1; level++; }
    int blk = r;
    int kblk = blk ^ 1;

    char* st = smem + warp * 6144;
    const uint32_t su = smem_to_u32(st);

    int off = 4096 - (8192 >> level);
    size_t pb = (size_t)bh * (POOLROWS * 64);
    const __half* qs = g_poolq + pb + (size_t)(off + blk * 16) * 64;
    const __half* ks = g_poolk + pb + (size_t)(off + kblk * 16) * 64;
    const __half* vs = g_poolv + pb + (size_t)(off + blk * 16) * 64;

    AttnOut o;
    attn_block_core(qs, ks, vs, 64, st, su, lane, o);

    int r0 = lane >> 2;
    int c0 = (lane & 3) * 2;
    __half* Ybase = g_Yc + pb + (size_t)(off + blk * 16) * 64;
#pragma unroll
    for (int f = 0; f < 8; f++) {
        int d0 = f * 8 + c0;
        *(__half2*)(Ybase + (size_t)r0 * 64 + d0)       = __floats2half2_rn(o.y[f][0], o.y[f][1]);
        *(__half2*)(Ybase + (size_t)(r0 + 8) * 64 + d0) = __floats2half2_rn(o.y[f][2], o.y[f][3]);
    }
    if ((lane & 3) == 0) {
        float* Ab = g_Ac + (size_t)bh * POOLROWS + off + blk * 16;
        Ab[r0] = o.sr;
        Ab[r0 + 8] = o.sr8;
    }
}

// ---------------- level-0 attention + inline coarse gather + combine -------
__global__ __launch_bounds__(256)
void attn0_combine(const __half* __restrict__ qkv)
{
    __shared__ __align__(1024) char smem[8 * 6144];
    int warp = threadIdx.x >> 5;
    int lane = threadIdx.x & 31;
    int wg = blockIdx.x * 8 + warp;            // [0, 8192)

    int bh = wg >> 8;
    int blk = wg & 255;
    int b = bh >> 3, h = bh & 7;

    char* st = smem + warp * 6144;
    const uint32_t su = smem_to_u32(st);

    size_t rq = (size_t)(b * 4096 + blk * 16) * QKVW;
    const __half* qs = qkv + rq + h * 64;
    const __half* ks = qkv + rq + 512 + h * 64;
    const __half* vs = qkv + rq + 1024 + h * 64;

    AttnOut o;
    attn_block_core(qs, ks, vs, QKVW, st, su, lane, o);

    // ---- gather coarse prefix (levels 1..7) into registers ----
    int n0 = blk * 16;
    int pbase = n0 >> 1;
    size_t pb = (size_t)bh * (POOLROWS * 64);
    const __half* Ycb = g_Yc + pb;
    const float* Acb = g_Ac + (size_t)bh * POOLROWS;

    int gr = lane >> 2;                 // this lane gathers prefix row gr (0..7)
    int gd = (lane & 3) * 16;           // 16 dims starting here
    float gacc[16];
#pragma unroll
    for (int i = 0; i < 16; i++) gacc[i] = 0.f;
    float ac = 0.f;
#pragma unroll
    for (int l = 1; l <= 7; l++) {
        int row = (4096 - (8192 >> l)) + ((pbase + gr) >> (l - 1));
        const __half* src = Ycb + (size_t)row * 64 + gd;
        float fa[8], fb[8];
        unpack8(*(const uint4*)(src), fa);
        unpack8(*(const uint4*)(src + 8), fb);
#pragma unroll
        for (int i = 0; i < 8; i++) { gacc[i] += fa[i]; gacc[8 + i] += fb[i]; }
        ac += Acb[row];
    }

    __syncwarp();                       // all smem reads in core done
    float* ys = (float*)st;             // 8 x 64 fp32 = 2048 B (reuse q region)
#pragma unroll
    for (int i = 0; i < 16; i++) ys[gr * 64 + gd + i] = gacc[i];
    __syncwarp();

    // ---- combine and emit fp16 att ----
    int r0 = lane >> 2;
    int c0 = (lane & 3) * 2;
    int p1 = r0 >> 1;
    int p2 = (r0 + 8) >> 1;
    float acA = __shfl_sync(0xffffffffu, ac, p1 * 4);
    float acB = __shfl_sync(0xffffffffu, ac, p2 * 4);
    float invA_r  = 1.f / (o.sr  + acA + 1e-8f);
    float invA_r8 = 1.f / (o.sr8 + acB + 1e-8f);

    __half* att_r  = g_atth + (size_t)(b * 4096 + n0 + r0) * 512 + h * 64;
    __half* att_r8 = g_atth + (size_t)(b * 4096 + n0 + r0 + 8) * 512 + h * 64;
#pragma unroll
    for (int f = 0; f < 8; f++) {
        int d0 = f * 8 + c0;
        float2 c_r  = *(float2*)&ys[p1 * 64 + d0];
        float2 c_r8 = *(float2*)&ys[p2 * 64 + d0];
        *(__half2*)(att_r + d0)  = __floats2half2_rn((o.y[f][0] + c_r.x) * invA_r,
                                                     (o.y[f][1] + c_r.y) * invA_r);
        *(__half2*)(att_r8 + d0) = __floats2half2_rn((o.y[f][2] + c_r8.x) * invA_r8,
                                                     (o.y[f][3] + c_r8.y) * invA_r8);
    }
}

// ---------------- Launch ----------------
extern "C" void kernel_launch(void* const* d_in, const int* in_sizes, int n_in,
                              void* d_out, int out_size)
{
    const float* x     = (const float*)d_in[0];
    const float* w_qkv = (const float*)d_in[1];
    const float* w_out = (const float*)d_in[2];
    const float* b_out = (const float*)d_in[3];
    float* out = (float*)d_out;

    __half *xh, *wqh, *woh, *ath, *qkv16;
    cudaGetSymbolAddress((void**)&xh, g_xh);
    cudaGetSymbolAddress((void**)&wqh, g_wqh);
    cudaGetSymbolAddress((void**)&woh, g_woh);
    cudaGetSymbolAddress((void**)&ath, g_atth);
    cudaGetSymbolAddress((void**)&qkv16, g_qkv16);

    cudaFuncSetAttribute(gemm_fp16<0>, cudaFuncAttributeMaxDynamicSharedMemorySize, GS_SMEM);
    cudaFuncSetAttribute(gemm_fp16<1>, cudaFuncAttributeMaxDynamicSharedMemorySize, GS_SMEM);

    // 1) Convert inputs to fp16
    convert_all<<<18432, 256>>>(x, w_qkv, w_out);

    // 2) QKV projection -> fp16 qkv (q pre-scaled 0.125)
    gemm_fp16<1><<<dim3(QKVW / 128, NROWS / 128), 256, GS_SMEM>>>(
        xh, wqh, nullptr, nullptr, qkv16, NROWS, QKVW, 1024);

    // 3) Fused pooling (fp16 planes, vectorized)
    pool_fused<<<dim3(32, 32), 256>>>(qkv16);

    // 4) Coarse attention (levels 1..7)
    attn_coarse<<<1016, 256>>>();

    // 5) Level-0 attention + inline coarse gather + combine -> fp16 att
    attn0_combine<<<1024, 256>>>(qkv16);

    // 6) Output projection (fp32 out + bias)
    gemm_fp16<0><<<dim3(1024 / 128, NROWS / 128), 256, GS_SMEM>>>(
        ath, woh, b_out, out, nullptr, NROWS, 1024, 512);
}